// round 10
// baseline (speedup 1.0000x reference)
#include <cuda_runtime.h>
#include <cuda_fp16.h>
#include <stdint.h>

// SNU on GB300 (base sm_103 ISA — mma.sync HMMA path):
//   out[b,h,t] = spike recurrence over xw[t,b,h] = sum_i x[b,i,t]*W[i,h]
//   B=128, I=512, H=512, T=512, DECAY=0.8
//
// Phase 1: transpose+split x -> fp16 pair (a0,a1) [b][t][i]; W -> (b0,b1) [h][i]
// Phase 2: FUSED GEMM+recurrence. CTA = (b, h-tile of 128). Runs the round-7
//          HMMA mainloop over 4 sequential t-chunks of 128, and after each
//          chunk applies the spike recurrence in smem (state in registers),
//          storing spikes directly to out.  No g_xw scratch round-trip.
// GEMM: K=3*512 segments (a0b0, a0b1, a1b0), fp32 HMMA accumulation.

typedef unsigned long long ull;

__device__ __half g_a0[33554432], g_a1[33554432];   // 65536 x 512 fp16 splits
__device__ __half g_b0[262144],  g_b1[262144];      // 512 x 512 fp16 splits

// ---------------------------------------------------------------- helpers ---
__device__ __forceinline__ uint32_t smem_u32(const void* p) {
    uint32_t a;
    asm("{ .reg .u64 t; cvta.to.shared.u64 t, %1; cvt.u32.u64 %0, t; }"
        : "=r"(a) : "l"(p));
    return a;
}
__device__ __forceinline__ void cp16(uint32_t dst, const void* src) {
    asm volatile("cp.async.cg.shared.global [%0], [%1], 16;"
                 :: "r"(dst), "l"(src) : "memory");
}
__device__ __forceinline__ void ldsm4(uint32_t a, uint32_t& r0, uint32_t& r1,
                                      uint32_t& r2, uint32_t& r3) {
    asm volatile("ldmatrix.sync.aligned.m8n8.x4.shared.b16 {%0,%1,%2,%3}, [%4];"
                 : "=r"(r0), "=r"(r1), "=r"(r2), "=r"(r3) : "r"(a));
}
__device__ __forceinline__ void mma16816(float* d, const uint32_t* a,
                                         uint32_t b0, uint32_t b1) {
    asm volatile(
        "mma.sync.aligned.m16n8k16.row.col.f32.f16.f16.f32 "
        "{%0,%1,%2,%3}, {%4,%5,%6,%7}, {%8,%9}, {%0,%1,%2,%3};"
        : "+f"(d[0]), "+f"(d[1]), "+f"(d[2]), "+f"(d[3])
        : "r"(a[0]), "r"(a[1]), "r"(a[2]), "r"(a[3]), "r"(b0), "r"(b1));
}

// ------------------------------------------------------------ convert pass ---
__device__ __forceinline__ void trans_split2(
    const float* __restrict__ src, size_t src_off, size_t dst_off,
    int r0, int c0, __half* __restrict__ d0, __half* __restrict__ d1,
    float smtile[64][65])
{
    const float* sp = src + src_off + (size_t)r0 * 512 + c0;
    for (int e = threadIdx.x; e < 1024; e += 256) {
        int r = e >> 4, c = (e & 15) << 2;
        float4 v = *(const float4*)(sp + (size_t)r * 512 + c);
        smtile[r][c] = v.x; smtile[r][c + 1] = v.y;
        smtile[r][c + 2] = v.z; smtile[r][c + 3] = v.w;
    }
    __syncthreads();
    size_t ob = dst_off + (size_t)c0 * 512 + r0;
    for (int e = threadIdx.x; e < 1024; e += 256) {
        int r = e >> 4, c = (e & 15) << 2;
        union { __half h[4]; ull u; } p0, p1;
        #pragma unroll
        for (int q = 0; q < 4; q++) {
            float v = smtile[c + q][r];
            __half h0 = __float2half_rn(v);
            float rr = v - __half2float(h0);
            __half h1 = __float2half_rn(rr);
            p0.h[q] = h0; p1.h[q] = h1;
        }
        size_t o = ob + (size_t)r * 512 + c;
        *(ull*)(d0 + o) = p0.u;
        *(ull*)(d1 + o) = p1.u;
    }
    __syncthreads();
}

__global__ __launch_bounds__(256) void convert_x_kernel(const float* __restrict__ x) {
    __shared__ float tile[64][65];
    size_t boff = (size_t)blockIdx.z * 262144;
    trans_split2(x, boff, boff, blockIdx.y * 64, blockIdx.x * 64, g_a0, g_a1, tile);
}
__global__ __launch_bounds__(256) void convert_w_kernel(const float* __restrict__ W) {
    __shared__ float tile[64][65];
    trans_split2(W, 0, 0, blockIdx.y * 64, blockIdx.x * 64, g_b0, g_b1, tile);
}

// ------------------------------------------------- fused GEMM + recurrence ---
// CTA tile 128(M) x 128(N) x 32(K-chunk), 256 threads = 8 warps (4m x 2n),
// warp tile 32x64, 4-stage cp.async pipeline (round-7 proven mainloop).
// Per CTA: 4 sequential m-tiles (t-chunks), recurrence state in registers.
// SMEM: stage area 4*20480 = 81920 B, aliased after drain by the fp32 xw tile
// [128][129] (66048 B, pitch 129 -> conflict-free column reads).

#define STG_B   20480
#define BPITCH  40

__global__ __launch_bounds__(256, 2) void gemm_recur(
    const float* __restrict__ bias, float* __restrict__ out)
{
    extern __shared__ __half smraw[];
    const uint32_t smb = smem_u32(smraw);
    float* xt = (float*)smraw;                      // [128][129] aliased on stages

    const int tid  = threadIdx.x;
    const int b    = blockIdx.x >> 2;
    const int n0   = (blockIdx.x & 3) * 128;        // h-tile
    const int wid  = tid >> 5, lane = tid & 31;
    const int mw   = (wid >> 1) * 32;
    const int nw   = (wid & 1) * 64;

    const int lrow = tid >> 1;
    const int lch  = (tid & 1) * 2;

    float hs = 0.0f, y = 0.0f, bb = 0.0f;
    if (tid < 128) bb = bias[n0 + tid];
    float* po = out + ((size_t)b * 512 + n0) * 512;     // + h*512 + t

    #define LOAD_CHUNK(c, slot, m0) do {                                      \
        int _seg  = (c) >> 4;                                                 \
        int _kloc = ((c) & 15) << 5;                                          \
        const __half* _ap = (_seg == 2) ? g_a1 : g_a0;                        \
        const __half* _bp = (_seg == 1) ? g_b1 : g_b0;                        \
        uint32_t _sA = smb + (slot) * STG_B + (lrow * BPITCH + lch * 8) * 2;  \
        const __half* _ag = _ap + ((m0) + lrow) * 512 + _kloc + lch * 8;      \
        const __half* _bg = _bp + (size_t)(n0 + lrow) * 512 + _kloc + lch * 8;\
        cp16(_sA,          _ag);  cp16(_sA + 16,          _ag + 8);           \
        cp16(_sA + 10240,  _bg);  cp16(_sA + 10240 + 16,  _bg + 8);           \
    } while (0)

    for (int mt = 0; mt < 4; mt++) {
        const size_t m0 = (size_t)b * 512 + mt * 128;

        float acc[2][8][4];
        #pragma unroll
        for (int i = 0; i < 2; i++)
            #pragma unroll
            for (int j = 0; j < 8; j++)
                #pragma unroll
                for (int q = 0; q < 4; q++) acc[i][j][q] = 0.0f;

        LOAD_CHUNK(0, 0, m0); asm volatile("cp.async.commit_group;" ::: "memory");
        LOAD_CHUNK(1, 1, m0); asm volatile("cp.async.commit_group;" ::: "memory");
        LOAD_CHUNK(2, 2, m0); asm volatile("cp.async.commit_group;" ::: "memory");

        for (int i = 0; i < 48; i++) {
            asm volatile("cp.async.wait_group 2;" ::: "memory");
            __syncthreads();
            if (i + 3 < 48) LOAD_CHUNK(i + 3, (i + 3) & 3, m0);
            asm volatile("cp.async.commit_group;" ::: "memory");

            const uint32_t base = smb + (i & 3) * STG_B;
            #pragma unroll
            for (int ks = 0; ks < 2; ks++) {
                const int col = ks * 16 + (lane >> 4) * 8;
                uint32_t ar[2][4], br[4][4];
                #pragma unroll
                for (int mi = 0; mi < 2; mi++) {
                    int row = mw + mi * 16 + (lane & 15);
                    ldsm4(base + (row * BPITCH + col) * 2,
                          ar[mi][0], ar[mi][1], ar[mi][2], ar[mi][3]);
                }
                #pragma unroll
                for (int nb = 0; nb < 4; nb++) {
                    int row = nw + nb * 16 + (lane & 15);
                    ldsm4(base + 10240 + (row * BPITCH + col) * 2,
                          br[nb][0], br[nb][1], br[nb][2], br[nb][3]);
                }
                #pragma unroll
                for (int mi = 0; mi < 2; mi++)
                    #pragma unroll
                    for (int nf = 0; nf < 8; nf++) {
                        int nb = nf >> 1, hh = nf & 1;
                        mma16816(acc[mi][nf], ar[mi], br[nb][hh], br[nb][hh + 2]);
                    }
            }
        }

        // drain async pipe, free stage smem for the xw tile
        asm volatile("cp.async.wait_group 0;" ::: "memory");
        __syncthreads();

        // acc -> smem tile [t_local][h_local], pitch 129
        // frag map: m = lane/4 (+8 for q>=2), n = 2*(lane%4) (+1 for odd q)
        #pragma unroll
        for (int mi = 0; mi < 2; mi++) {
            int r0 = mw + mi * 16 + (lane >> 2);
            #pragma unroll
            for (int nf = 0; nf < 8; nf++) {
                int c0 = nw + nf * 8 + ((lane & 3) << 1);
                xt[r0 * 129 + c0]           = acc[mi][nf][0];
                xt[r0 * 129 + c0 + 1]       = acc[mi][nf][1];
                xt[(r0 + 8) * 129 + c0]     = acc[mi][nf][2];
                xt[(r0 + 8) * 129 + c0 + 1] = acc[mi][nf][3];
            }
        }
        __syncthreads();

        // recurrence over the 128 local timesteps; spikes written in place
        if (tid < 128) {
            float v = xt[tid];
            #pragma unroll 4
            for (int t = 0; t < 128; t++) {
                float vn = (t < 127) ? xt[(t + 1) * 129 + tid] : 0.0f;
                hs = fmaxf(v + 0.8f * hs * (1.0f - y), 0.0f);
                y  = (hs + bb > 0.0f) ? 1.0f : 0.0f;
                xt[t * 129 + tid] = y;
                v = vn;
            }
        }
        __syncthreads();

        // coalesced [h][t] stores: warp r handles rows hh0+r; lanes cover t
        {
            const int r = tid >> 5, c = tid & 31;
            #pragma unroll
            for (int hh0 = 0; hh0 < 128; hh0 += 8) {
                int hh = hh0 + r;
                float4 v;
                v.x = xt[(c * 4 + 0) * 129 + hh];
                v.y = xt[(c * 4 + 1) * 129 + hh];
                v.z = xt[(c * 4 + 2) * 129 + hh];
                v.w = xt[(c * 4 + 3) * 129 + hh];
                *(float4*)(po + (size_t)hh * 512 + mt * 128 + c * 4) = v;
            }
        }
        __syncthreads();
    }
}

// ------------------------------------------------------------------- launch ---
extern "C" void kernel_launch(void* const* d_in, const int* in_sizes, int n_in,
                              void* d_out, int out_size)
{
    const float* x = (const float*)d_in[0];   // (128, 512, 512)
    const float* W = (const float*)d_in[1];   // (512, 512)
    const float* b = (const float*)d_in[2];   // (1, 512)
    float* out = (float*)d_out;               // (128, 512, 512) float32

    cudaFuncSetAttribute(gemm_recur,
                         cudaFuncAttributeMaxDynamicSharedMemorySize, 4 * STG_B);

    convert_x_kernel<<<dim3(8, 8, 128), 256>>>(x);
    convert_w_kernel<<<dim3(8, 8), 256>>>(W);
    gemm_recur<<<512, 256, 4 * STG_B>>>(b, out);
}

// round 11
// speedup vs baseline: 1.3052x; 1.3052x over previous
#include <cuda_runtime.h>
#include <cuda_fp16.h>
#include <stdint.h>

// SNU on GB300 (base sm_103 ISA — mma.sync HMMA path):
//   out[b,h,t] = spike recurrence over xw[t,b,h] = sum_i x[b,i,t]*W[i,h]
//   B=128, I=512, H=512, T=512, DECAY=0.8
//
// v5 structure:
//  - convert_w: W -> fp16 split pair (b0,b1) [h][i]          (~4 us)
//  - gemm_fc:   A-side convert FUSED into GEMM: loads raw fp32 x blocks
//               (contiguous in native layout), builds fp16 split A-fragments
//               in registers, 3 products a0b0+a0b1+a1b0 into fp32 HMMA acc.
//               CTA tile 128m x 64n, warp tile 32x32, 4-stage cp.async.
//  - recur v2:  2-buffer cp.async staged spike recurrence    (~62 us)

typedef unsigned long long ull;

__device__ float  g_xw[33554432];               // 65536 x 512 fp32
__device__ __half g_b0[262144], g_b1[262144];   // 512 x 512 fp16 splits of W^T

// ---------------------------------------------------------------- helpers ---
__device__ __forceinline__ uint32_t smem_u32(const void* p) {
    uint32_t a;
    asm("{ .reg .u64 t; cvta.to.shared.u64 t, %1; cvt.u32.u64 %0, t; }"
        : "=r"(a) : "l"(p));
    return a;
}
__device__ __forceinline__ void cp16(uint32_t dst, const void* src) {
    asm volatile("cp.async.cg.shared.global [%0], [%1], 16;"
                 :: "r"(dst), "l"(src) : "memory");
}
__device__ __forceinline__ void ldsm4(uint32_t a, uint32_t& r0, uint32_t& r1,
                                      uint32_t& r2, uint32_t& r3) {
    asm volatile("ldmatrix.sync.aligned.m8n8.x4.shared.b16 {%0,%1,%2,%3}, [%4];"
                 : "=r"(r0), "=r"(r1), "=r"(r2), "=r"(r3) : "r"(a));
}
__device__ __forceinline__ void mma16816(float* d, const uint32_t* a,
                                         uint32_t b0, uint32_t b1) {
    asm volatile(
        "mma.sync.aligned.m16n8k16.row.col.f32.f16.f16.f32 "
        "{%0,%1,%2,%3}, {%4,%5,%6,%7}, {%8,%9}, {%0,%1,%2,%3};"
        : "+f"(d[0]), "+f"(d[1]), "+f"(d[2]), "+f"(d[3])
        : "r"(a[0]), "r"(a[1]), "r"(a[2]), "r"(a[3]), "r"(b0), "r"(b1));
}
// split pair {even,odd} fp32 -> (a0 f16x2, a1 f16x2); lo half = even col
__device__ __forceinline__ void split_pair(float ve, float vo,
                                           uint32_t& r0, uint32_t& r1) {
    __half2 h = __floats2half2_rn(ve, vo);
    float2  w = __half22float2(h);
    __half2 g = __floats2half2_rn(ve - w.x, vo - w.y);
    r0 = *(uint32_t*)&h;
    r1 = *(uint32_t*)&g;
}

// ------------------------------------------------------------ convert_w ---
__global__ __launch_bounds__(256) void convert_w_kernel(const float* __restrict__ W) {
    __shared__ float tile[64][65];
    int r0 = blockIdx.y * 64, c0 = blockIdx.x * 64;
    const float* sp = W + (size_t)r0 * 512 + c0;
    for (int e = threadIdx.x; e < 1024; e += 256) {
        int r = e >> 4, c = (e & 15) << 2;
        float4 v = *(const float4*)(sp + (size_t)r * 512 + c);
        tile[r][c] = v.x; tile[r][c + 1] = v.y;
        tile[r][c + 2] = v.z; tile[r][c + 3] = v.w;
    }
    __syncthreads();
    size_t ob = (size_t)c0 * 512 + r0;
    for (int e = threadIdx.x; e < 1024; e += 256) {
        int r = e >> 4, c = (e & 15) << 2;
        union { __half h[4]; ull u; } p0, p1;
        #pragma unroll
        for (int q = 0; q < 4; q++) {
            float v = tile[c + q][r];
            __half h0 = __float2half_rn(v);
            float rr = v - __half2float(h0);
            p0.h[q] = h0; p1.h[q] = __float2half_rn(rr);
        }
        size_t o = ob + (size_t)r * 512 + c;
        *(ull*)(g_b0 + o) = p0.u;
        *(ull*)(g_b1 + o) = p1.u;
    }
}

// ------------------------------------------------ GEMM w/ fused A-convert ---
// CTA 128(M) x 64(N) x 32(K-chunk), 256 thr = 8 warps (4m x 2n), warp 32x32.
// Stage (27136 B): X fp32 32x132 pitch (16896) + b0 64x40h (5120) + b1 (5120).
// 4 stages = 108544 B.  16 k-chunks; per chunk 3 split-products -> same acc.

#define STG    27136
#define XPITCH 132

__global__ __launch_bounds__(256, 2) void gemm_fc(const float* __restrict__ x) {
    extern __shared__ char smraw[];
    const uint32_t smb = smem_u32(smraw);

    const int tid  = threadIdx.x;
    const int n0   = blockIdx.x * 64;
    const int mt   = blockIdx.y;                 // m-tile 0..511
    const int b    = mt >> 2;
    const int t0   = (mt & 3) * 128;
    const int wid  = tid >> 5, lane = tid & 31;
    const int mw   = (wid >> 1) * 32;
    const int nw   = (wid & 1) * 32;

    const float* xb = x + (size_t)b * 262144 + t0;   // + k*512 + t

    float acc[2][4][4];
    #pragma unroll
    for (int i = 0; i < 2; i++)
        #pragma unroll
        for (int j = 0; j < 4; j++)
            #pragma unroll
            for (int q = 0; q < 4; q++) acc[i][j][q] = 0.0f;

    // X: 4 cp16/thread (1024 total); B: 2 cp16/thread (512 total)
    #define LOAD_CHUNK(c, slot) do {                                          \
        int _k0 = (c) << 5;                                                   \
        uint32_t _sb = smb + (slot) * STG;                                    \
        _Pragma("unroll")                                                     \
        for (int _q = 0; _q < 4; _q++) {                                      \
            int _e = tid + 256 * _q;                                          \
            int _r = _e >> 5, _c = _e & 31;                                   \
            cp16(_sb + _r * (XPITCH * 4) + _c * 16,                           \
                 xb + (size_t)(_k0 + _r) * 512 + _c * 4);                     \
        }                                                                     \
        {                                                                     \
            int _r = tid >> 2, _c4 = tid & 3;                                 \
            cp16(_sb + 16896 + _r * 80 + _c4 * 16,                            \
                 g_b0 + (size_t)(n0 + _r) * 512 + _k0 + _c4 * 8);             \
            cp16(_sb + 22016 + _r * 80 + _c4 * 16,                            \
                 g_b1 + (size_t)(n0 + _r) * 512 + _k0 + _c4 * 8);             \
        }                                                                     \
    } while (0)

    LOAD_CHUNK(0, 0); asm volatile("cp.async.commit_group;" ::: "memory");
    LOAD_CHUNK(1, 1); asm volatile("cp.async.commit_group;" ::: "memory");
    LOAD_CHUNK(2, 2); asm volatile("cp.async.commit_group;" ::: "memory");

    for (int i = 0; i < 16; i++) {
        asm volatile("cp.async.wait_group 2;" ::: "memory");
        __syncthreads();
        if (i + 3 < 16) LOAD_CHUNK(i + 3, (i + 3) & 3);
        asm volatile("cp.async.commit_group;" ::: "memory");

        const int slot = i & 3;
        const float* Xs = (const float*)(smraw + slot * STG);
        const uint32_t bbase = smb + slot * STG + 16896;

        // ---- build A fragments (a0 + a1 splits) for all (mi, ks) ----
        uint32_t ar0[2][2][4], ar1[2][2][4];
        #pragma unroll
        for (int mi = 0; mi < 2; mi++) {
            #pragma unroll
            for (int ks = 0; ks < 2; ks++) {
                const int tq = mw + mi * 16 + (lane >> 2);
                const int kq = ks * 16 + (lane & 3) * 2;
                const float* p = Xs + kq * XPITCH + tq;
                // j0: (tq, kq/kq+1)  j1: t+8  j2: k+8  j3: t+8,k+8
                split_pair(p[0],              p[XPITCH],
                           ar0[mi][ks][0], ar1[mi][ks][0]);
                split_pair(p[8],              p[XPITCH + 8],
                           ar0[mi][ks][1], ar1[mi][ks][1]);
                split_pair(p[8 * XPITCH],     p[9 * XPITCH],
                           ar0[mi][ks][2], ar1[mi][ks][2]);
                split_pair(p[8 * XPITCH + 8], p[9 * XPITCH + 8],
                           ar0[mi][ks][3], ar1[mi][ks][3]);
            }
        }

        // ---- MMA: 3 products into the same accumulators ----
        #pragma unroll
        for (int ks = 0; ks < 2; ks++) {
            const int col = ks * 16 + (lane >> 4) * 8;
            uint32_t br0[2][4], br1[2][4];
            #pragma unroll
            for (int nb = 0; nb < 2; nb++) {
                int row = nw + nb * 16 + (lane & 15);
                ldsm4(bbase + (row * 40 + col) * 2,
                      br0[nb][0], br0[nb][1], br0[nb][2], br0[nb][3]);
                ldsm4(bbase + 5120 + (row * 40 + col) * 2,
                      br1[nb][0], br1[nb][1], br1[nb][2], br1[nb][3]);
            }
            #pragma unroll
            for (int mi = 0; mi < 2; mi++)
                #pragma unroll
                for (int nf = 0; nf < 4; nf++) {
                    int nb = nf >> 1, hh = nf & 1;
                    mma16816(acc[mi][nf], ar0[mi][ks], br0[nb][hh], br0[nb][hh + 2]);
                    mma16816(acc[mi][nf], ar0[mi][ks], br1[nb][hh], br1[nb][hh + 2]);
                    mma16816(acc[mi][nf], ar1[mi][ks], br0[nb][hh], br0[nb][hh + 2]);
                }
        }
    }

    // epilogue: frag map m = lane/4 (+8), n = 2*(lane%4) (+1)
    #pragma unroll
    for (int mi = 0; mi < 2; mi++) {
        int row = mt * 128 + mw + mi * 16 + (lane >> 2);
        #pragma unroll
        for (int nf = 0; nf < 4; nf++) {
            int col = n0 + nw + nf * 8 + ((lane & 3) << 1);
            *(float2*)(g_xw + (size_t)row * 512 + col) =
                make_float2(acc[mi][nf][0], acc[mi][nf][1]);
            *(float2*)(g_xw + (size_t)(row + 8) * 512 + col) =
                make_float2(acc[mi][nf][2], acc[mi][nf][3]);
        }
    }
}

// ---------------------------------------------------------------- recurrence ---
// v2 (round-8 proven, 62us): 2-buffer cp.async staging.
// Dynamic smem: in[2][32][128] (32KB) + outbuf[128][33] (16.9KB) = 49664 B
__global__ __launch_bounds__(128) void recur_kernel(
    const float* __restrict__ bias, float* __restrict__ out)
{
    extern __shared__ float dyn[];
    float* smin = dyn;                               // [2][32*128]
    float (*buf)[33] = (float(*)[33])(dyn + 8192);   // [128][33]

    const int b  = blockIdx.x >> 2;
    const int h0 = (blockIdx.x & 3) * 128;
    const int h  = h0 + threadIdx.x;
    const int tid = threadIdx.x;

    const float bb = bias[h];
    float hs = 0.0f, y = 0.0f;

    const float* gx = g_xw + ((size_t)b * 512) * 512 + h0;
    float*       po = out + ((size_t)b * 512 + h0) * 512;

    const uint32_t smin_u = smem_u32(smin);
    const int lrow = tid >> 2;
    const int lq   = (tid & 3) * 32;

    #define RLOAD(tc0, bsel) do {                                             \
        const float* _src = gx + (size_t)((tc0) + lrow) * 512 + lq;           \
        uint32_t _dst = smin_u + (((bsel) * 4096 + lrow * 128 + lq) * 4);     \
        cp16(_dst,      _src);      cp16(_dst + 16, _src + 4);                \
        cp16(_dst + 32, _src + 8);  cp16(_dst + 48, _src + 12);               \
        cp16(_dst + 64, _src + 16); cp16(_dst + 80, _src + 20);               \
        cp16(_dst + 96, _src + 24); cp16(_dst + 112, _src + 28);              \
    } while (0)

    RLOAD(0, 0);
    asm volatile("cp.async.commit_group;" ::: "memory");

    for (int tc = 0; tc < 16; tc++) {
        if (tc < 15) {
            RLOAD((tc + 1) * 32, (tc + 1) & 1);
            asm volatile("cp.async.commit_group;" ::: "memory");
            asm volatile("cp.async.wait_group 1;" ::: "memory");
        } else {
            asm volatile("cp.async.wait_group 0;" ::: "memory");
        }
        __syncthreads();

        const float* cs = smin + (tc & 1) * 4096;
        #pragma unroll
        for (int j = 0; j < 32; j++) {
            float v = cs[j * 128 + tid];
            hs = fmaxf(v + 0.8f * hs * (1.0f - y), 0.0f);
            y  = (hs + bb > 0.0f) ? 1.0f : 0.0f;
            buf[tid][j] = y;
        }
        __syncthreads();
        const int r = tid >> 5;
        const int c = tid & 31;
        #pragma unroll
        for (int rr = 0; rr < 128; rr += 4)
            po[(size_t)(rr + r) * 512 + tc * 32 + c] = buf[rr + r][c];
        __syncthreads();
    }
}

// ------------------------------------------------------------------- launch ---
extern "C" void kernel_launch(void* const* d_in, const int* in_sizes, int n_in,
                              void* d_out, int out_size)
{
    const float* x = (const float*)d_in[0];   // (128, 512, 512)
    const float* W = (const float*)d_in[1];   // (512, 512)
    const float* b = (const float*)d_in[2];   // (1, 512)
    float* out = (float*)d_out;               // (128, 512, 512) float32

    cudaFuncSetAttribute(gemm_fc,
                         cudaFuncAttributeMaxDynamicSharedMemorySize, 4 * STG);
    cudaFuncSetAttribute(recur_kernel,
                         cudaFuncAttributeMaxDynamicSharedMemorySize, 49664);

    convert_w_kernel<<<dim3(8, 8), 256>>>(W);
    gemm_fc<<<dim3(8, 512), 256, 4 * STG>>>(x);
    recur_kernel<<<512, 128, 49664>>>(b, out);
}